// round 4
// baseline (speedup 1.0000x reference)
#include <cuda_runtime.h>
#include <math.h>
#include <stdint.h>

#define NPOS    80
#define HID     128

// ---- scratch: post-ELU h0 (padded past 8192 rows for safe OOB-row reads) ----
#define MAXB 8192
__device__ float g_h0[(MAXB + 64) * HID];
__device__ int   g_msg_is64;

__global__ void detect_kernel(const int* __restrict__ msg) {
    int t = threadIdx.x;
    int v = 0;
    #pragma unroll 4
    for (int i = t; i < 2048; i += 32) v |= msg[2 * i + 1];
    unsigned ball = __ballot_sync(0xFFFFFFFFu, v != 0);
    if (t == 0) g_msg_is64 = (ball == 0u) ? 1 : 0;
}

__device__ __forceinline__ float elu1(float x) {
    return x > 0.0f ? x : expm1f(x);
}

// ---- f32x2 packed helpers ----
__device__ __forceinline__ unsigned long long pk2(float lo, float hi) {
    unsigned long long r;
    asm("mov.b64 %0, {%1, %2};" : "=l"(r) : "f"(lo), "f"(hi));
    return r;
}
__device__ __forceinline__ void upk2(unsigned long long v, float& lo, float& hi) {
    asm("mov.b64 {%0, %1}, %2;" : "=f"(lo), "=f"(hi) : "l"(v));
}
__device__ __forceinline__ void fma2(unsigned long long& d,
                                     unsigned long long a, unsigned long long b) {
    asm("fma.rn.f32x2 %0, %1, %2, %0;" : "+l"(d) : "l"(a), "l"(b));
}
__device__ __forceinline__ void add2(unsigned long long& d, unsigned long long a) {
    asm("add.rn.f32x2 %0, %0, %1;" : "+l"(d) : "l"(a));
}

// ============================================================================
// Phase 1: gather. 16 rows/CTA, 128 threads (4 warps x 4 rows, lane = float4 col)
// Tiny footprint -> ~all CTAs resident -> enough MLP to saturate L2.
// ============================================================================
#define GTILE 16
#define GTHREADS 128

__global__ __launch_bounds__(GTHREADS)
void gather_kernel(const int* __restrict__ msg,
                   const float* __restrict__ W1, const float* __restrict__ b1,
                   int B)
{
    __shared__ unsigned char msg_sh[NPOS * GTILE];   // [p][r], 1280 B

    const int t    = threadIdx.x;
    const int row0 = blockIdx.x * GTILE;
    const int is64 = g_msg_is64;

    for (int idx = t; idx < NPOS * GTILE; idx += GTHREADS) {
        int p = idx >> 4;
        int r = idx & 15;
        int row = row0 + r;
        int c = 0;
        if (row < B) {
            int gi = row * NPOS + p;
            c = is64 ? msg[2 * gi] : msg[gi];
        }
        msg_sh[idx] = (unsigned char)c;
    }
    __syncthreads();

    const int h4 = t & 31;      // float4 hid column (lane)
    const int wr = t >> 5;      // warp -> rows wr*4 .. wr*4+3

    unsigned long long acc[4][2];
    {
        float4 bias1 = __ldg(&((const float4*)b1)[h4]);
        unsigned long long blo = pk2(bias1.x, bias1.y);
        unsigned long long bhi = pk2(bias1.z, bias1.w);
        #pragma unroll
        for (int i = 0; i < 4; i++) { acc[i][0] = blo; acc[i][1] = bhi; }
    }

    const float4* W1v = (const float4*)W1 + h4;
    #pragma unroll 2
    for (int p = 0; p < NPOS; p++) {
        unsigned c4 = *(const unsigned*)(msg_sh + p * GTILE + wr * 4);
        const float4* Wp = W1v + (p << 13);        // + p*256*128/4
        #pragma unroll
        for (int i = 0; i < 4; i++) {
            int c = (c4 >> (8 * i)) & 255;
            float4 w = __ldg(Wp + (c << 5));       // coalesced 512B per warp
            ulonglong2 uw = *(ulonglong2*)&w;
            add2(acc[i][0], uw.x);
            add2(acc[i][1], uw.y);
        }
    }

    #pragma unroll
    for (int i = 0; i < 4; i++) {
        int row = row0 + wr * 4 + i;
        if (row < B) {
            float4 v;
            upk2(acc[i][0], v.x, v.y);
            upk2(acc[i][1], v.z, v.w);
            v.x = elu1(v.x); v.y = elu1(v.y); v.z = elu1(v.z); v.w = elu1(v.w);
            ((float4*)g_h0)[row * 32 + h4] = v;
        }
    }
}

// ============================================================================
// Phase 2: 3 dense layers. 28 rows/CTA, 224 threads, grid ~2*148 (balanced).
// Thread tile 4 rows x 4 cols, f32x2 accumulators paired over k-parity.
// ============================================================================
#define MTILE 28
#define MTHREADS 224
// smem: Wsh 64KB + hA 14KB + hB 14KB = 92KB
#define MSMEM_FLOATS (16384 + MTILE * HID * 2)
#define MSMEM_BYTES  (MSMEM_FLOATS * 4)

__global__ __launch_bounds__(MTHREADS, 2)
void mlp_kernel(const float* __restrict__ W2, const float* __restrict__ b2,
                const float* __restrict__ W3, const float* __restrict__ b3,
                const float* __restrict__ W4, const float* __restrict__ b4,
                float* __restrict__ out, int B)
{
    extern __shared__ float smem[];
    float4* Wsh4 = (float4*)smem;
    float4* hA4  = (float4*)(smem + 16384);
    float4* hB4  = (float4*)(smem + 16384 + MTILE * HID);

    const int t    = threadIdx.x;
    const int row0 = blockIdx.x * MTILE;

    // Load h0 tile (already ELU'd) into hA
    for (int idx = t; idx < MTILE * 32; idx += MTHREADS) {
        hA4[idx] = ((const float4*)g_h0)[row0 * 32 + idx];
    }

    const int j4 = t & 31;          // float4 column
    const int r0 = (t >> 5) * 4;    // 4 rows (7 warps x 4 = 28)

    const float* Wg[3] = {W2, W3, W4};
    const float* bg[3] = {b2, b3, b4};

    #pragma unroll 1
    for (int layer = 0; layer < 3; layer++) {
        const float4* hin  = (layer == 1) ? hB4 : hA4;
        float4*       hout = (layer == 1) ? hA4 : hB4;
        const bool    last = (layer == 2);

        const float4* Wg4 = (const float4*)Wg[layer];
        #pragma unroll 4
        for (int i = t; i < 4096; i += MTHREADS) Wsh4[i] = __ldg(&Wg4[i]);
        __syncthreads();

        unsigned long long a[4][4];   // [row][col], f32x2 over k-parity
        {
            float4 bias = __ldg(&((const float4*)bg[layer])[j4]);
            #pragma unroll
            for (int r = 0; r < 4; r++) {
                a[r][0] = pk2(bias.x, 0.0f);
                a[r][1] = pk2(bias.y, 0.0f);
                a[r][2] = pk2(bias.z, 0.0f);
                a[r][3] = pk2(bias.w, 0.0f);
            }
        }

        #pragma unroll 4
        for (int k4 = 0; k4 < 32; k4++) {
            float4 w0 = Wsh4[(4 * k4 + 0) * 32 + j4];
            float4 w1 = Wsh4[(4 * k4 + 1) * 32 + j4];
            float4 w2 = Wsh4[(4 * k4 + 2) * 32 + j4];
            float4 w3 = Wsh4[(4 * k4 + 3) * 32 + j4];
            unsigned long long wp0[4], wp1[4];
            wp0[0] = pk2(w0.x, w1.x); wp0[1] = pk2(w0.y, w1.y);
            wp0[2] = pk2(w0.z, w1.z); wp0[3] = pk2(w0.w, w1.w);
            wp1[0] = pk2(w2.x, w3.x); wp1[1] = pk2(w2.y, w3.y);
            wp1[2] = pk2(w2.z, w3.z); wp1[3] = pk2(w2.w, w3.w);
            #pragma unroll
            for (int r = 0; r < 4; r++) {
                ulonglong2 hv = *(const ulonglong2*)&hin[(r0 + r) * 32 + k4];
                fma2(a[r][0], hv.x, wp0[0]);
                fma2(a[r][1], hv.x, wp0[1]);
                fma2(a[r][2], hv.x, wp0[2]);
                fma2(a[r][3], hv.x, wp0[3]);
                fma2(a[r][0], hv.y, wp1[0]);
                fma2(a[r][1], hv.y, wp1[1]);
                fma2(a[r][2], hv.y, wp1[2]);
                fma2(a[r][3], hv.y, wp1[3]);
            }
        }

        if (!last) {
            #pragma unroll
            for (int r = 0; r < 4; r++) {
                float4 v; float lo, hi;
                upk2(a[r][0], lo, hi); v.x = elu1(lo + hi);
                upk2(a[r][1], lo, hi); v.y = elu1(lo + hi);
                upk2(a[r][2], lo, hi); v.z = elu1(lo + hi);
                upk2(a[r][3], lo, hi); v.w = elu1(lo + hi);
                hout[(r0 + r) * 32 + j4] = v;
            }
            __syncthreads();
        } else {
            #pragma unroll
            for (int r = 0; r < 4; r++) {
                int row = row0 + r0 + r;
                if (row < B) {
                    float4 v; float lo, hi;
                    upk2(a[r][0], lo, hi); v.x = elu1(lo + hi);
                    upk2(a[r][1], lo, hi); v.y = elu1(lo + hi);
                    upk2(a[r][2], lo, hi); v.z = elu1(lo + hi);
                    upk2(a[r][3], lo, hi); v.w = elu1(lo + hi);
                    ((float4*)out)[row * 32 + j4] = v;
                }
            }
        }
    }
}

extern "C" void kernel_launch(void* const* d_in, const int* in_sizes, int n_in,
                              void* d_out, int out_size)
{
    const int*   msg = (const int*)  d_in[0];
    const float* W1  = (const float*)d_in[1];
    const float* b1  = (const float*)d_in[2];
    const float* W2  = (const float*)d_in[3];
    const float* b2  = (const float*)d_in[4];
    const float* W3  = (const float*)d_in[5];
    const float* b3  = (const float*)d_in[6];
    const float* W4  = (const float*)d_in[7];
    const float* b4  = (const float*)d_in[8];
    float* out = (float*)d_out;

    const int B = in_sizes[0] / NPOS;   // 8192

    cudaFuncSetAttribute(mlp_kernel,
                         cudaFuncAttributeMaxDynamicSharedMemorySize, MSMEM_BYTES);

    detect_kernel<<<1, 32>>>(msg);

    int ggrid = (B + GTILE - 1) / GTILE;   // 512
    gather_kernel<<<ggrid, GTHREADS>>>(msg, W1, b1, B);

    int mgrid = (B + MTILE - 1) / MTILE;   // 293 ~= 2 * 148
    mlp_kernel<<<mgrid, MTHREADS, MSMEM_BYTES>>>(W2, b2, W3, b3, W4, b4, out, B);
}